// round 1
// baseline (speedup 1.0000x reference)
#include <cuda_runtime.h>

// Problem constants
#define Bq   8
#define Cc   256
#define HWp  4096          // 64*64
#define Nn   1024
#define Dd   256
#define PIX  (Bq*HWp)      // 32768 pixels

// Tiling
#define TP   128           // pixels per block
#define TN   128           // n per chunk
#define KC   32            // c per k-stage
#define NCHUNK (Nn/TN)     // 8
#define KSTG   (Cc/KC)     // 8
#define WS   132           // w_s row stride (pad)
#define GS   257           // gather row stride (pad, conflict-free transpose)

// Output layout: [z_q (8*256*64*64) | diff (1) | ind (8*64*64)] as float32
#define ZQ_SIZE  (Bq*Dd*HWp)
#define DIFF_OFF ZQ_SIZE
#define IND_OFF  (ZQ_SIZE+1)

// Dynamic smem: z_s (256*128) + w_s (32*132) floats = 36992 floats = 147968 B
// Gather reuse needs 128*257 = 32896 floats < 36992. OK.
#define SMEM_FLOATS (Cc*TP + KC*WS)
#define SMEM_BYTES  (SMEM_FLOATS * 4)

extern __shared__ float sm_dyn[];

__global__ __launch_bounds__(256, 1)
void aq_kernel(const float* __restrict__ z,
               const float* __restrict__ pw,
               const float* __restrict__ pb,
               const float* __restrict__ emb,
               float* __restrict__ out)
{
    float* z_s = sm_dyn;            // [Cc][TP]  (c-major, matches z layout)
    float* w_s = sm_dyn + Cc * TP;  // [KC][WS]  (c-major, transposed on load)
    __shared__ int s_idx[TP];

    const int tid  = threadIdx.x;
    const int pix0 = blockIdx.x * TP;          // global pixel base
    const int b    = pix0 >> 12;               // /4096 (tile never crosses batch)
    const int hw0  = pix0 & (HWp - 1);
    const float* zb = z + (size_t)b * Cc * HWp + hw0;

    // ---- Load full z tile [256 c][128 p] into smem (coalesced, once) ----
    #pragma unroll
    for (int i = 0; i < 32; i++) {
        int e4 = tid + i * 256;                // 8192 float4s total
        int c  = e4 >> 5;                      // 32 float4 per c-row
        int p4 = (e4 & 31) << 2;
        float4 v = *(const float4*)(zb + (size_t)c * HWp + p4);
        *(float4*)(z_s + c * TP + p4) = v;
    }
    // (first __syncthreads inside k-loop orders these stores before compute)

    const int tx = tid & 15;   // n sub-tile (8 n's each)
    const int ty = tid >> 4;   // pixel row  (8 pixels each)

    float bestV[8];
    int   bestI[8];
    #pragma unroll
    for (int i = 0; i < 8; i++) { bestV[i] = -3.4e38f; bestI[i] = 0; }

    for (int nc = 0; nc < NCHUNK; nc++) {
        const int nBase = nc * TN;
        float acc[8][8];
        #pragma unroll
        for (int i = 0; i < 8; i++)
            #pragma unroll
            for (int j = 0; j < 8; j++) acc[i][j] = 0.0f;

        for (int ks = 0; ks < KSTG; ks++) {
            // ---- stage w chunk [128 n][32 c] -> w_s[c][n] (transposed) ----
            #pragma unroll
            for (int i = 0; i < 4; i++) {
                int e  = tid + i * 256;        // 1024 float4s
                int n  = e >> 3;               // 8 float4 per n-row
                int c4 = (e & 7) << 2;
                float4 v = *(const float4*)(pw + (size_t)(nBase + n) * Cc + ks * KC + c4);
                w_s[(c4 + 0) * WS + n] = v.x;
                w_s[(c4 + 1) * WS + n] = v.y;
                w_s[(c4 + 2) * WS + n] = v.z;
                w_s[(c4 + 3) * WS + n] = v.w;
            }
            __syncthreads();

            #pragma unroll
            for (int c = 0; c < KC; c++) {
                const float* zr = z_s + (ks * KC + c) * TP + ty * 8;
                const float* wr = w_s + c * WS + tx * 8;
                float4 z0 = *(const float4*)zr;
                float4 z1 = *(const float4*)(zr + 4);
                float4 w0 = *(const float4*)wr;
                float4 w1 = *(const float4*)(wr + 4);
                float zv[8] = {z0.x, z0.y, z0.z, z0.w, z1.x, z1.y, z1.z, z1.w};
                float wv[8] = {w0.x, w0.y, w0.z, w0.w, w1.x, w1.y, w1.z, w1.w};
                #pragma unroll
                for (int i = 0; i < 8; i++)
                    #pragma unroll
                    for (int j = 0; j < 8; j++)
                        acc[i][j] = fmaf(zv[i], wv[j], acc[i][j]);
            }
            __syncthreads();
        }

        // ---- bias + fused argmax for this n-chunk ----
        float4 b0 = *(const float4*)(pb + nBase + tx * 8);
        float4 b1 = *(const float4*)(pb + nBase + tx * 8 + 4);
        float bias[8] = {b0.x, b0.y, b0.z, b0.w, b1.x, b1.y, b1.z, b1.w};

        #pragma unroll
        for (int i = 0; i < 8; i++) {
            float v  = acc[i][0] + bias[0];
            int  idx = nBase + tx * 8;
            #pragma unroll
            for (int j = 1; j < 8; j++) {
                float t = acc[i][j] + bias[j];
                if (t > v) { v = t; idx = nBase + tx * 8 + j; }   // strict >: keep earliest
            }
            // butterfly over the 16 tx lanes (never crosses half-warp: xor<=8)
            #pragma unroll
            for (int s = 1; s < 16; s <<= 1) {
                float ov = __shfl_xor_sync(0xffffffffu, v, s);
                int   oi = __shfl_xor_sync(0xffffffffu, idx, s);
                if (ov > v || (ov == v && oi < idx)) { v = ov; idx = oi; }
            }
            if (v > bestV[i] || (v == bestV[i] && idx < bestI[i])) {
                bestV[i] = v; bestI[i] = idx;
            }
        }
    }

    if (tx == 0) {
        #pragma unroll
        for (int i = 0; i < 8; i++) s_idx[ty * 8 + i] = bestI[i];
    }
    __syncthreads();

    // ---- write ind (as float) and diff ----
    if (tid < TP) out[IND_OFF + pix0 + tid] = (float)s_idx[tid];
    if (blockIdx.x == 0 && tid == 0) out[DIFF_OFF] = 0.0f;

    // ---- gather epilogue: z_q[b, d, hw] = embed[ind, d] ----
    // Phase A: coalesced row-gather embed[idx[p]][:] -> g_s[p][d] (pad 257)
    float* g_s = sm_dyn;   // reuse (z_s/w_s dead after sync above)
    #pragma unroll 4
    for (int it = 0; it < 32; it++) {
        int e4 = tid + it * 256;               // 8192 float4s
        int p  = e4 >> 6;                      // 64 float4 per row
        int d4 = (e4 & 63) << 2;
        float4 v = *(const float4*)(emb + (size_t)s_idx[p] * Dd + d4);
        g_s[p * GS + d4 + 0] = v.x;
        g_s[p * GS + d4 + 1] = v.y;
        g_s[p * GS + d4 + 2] = v.z;
        g_s[p * GS + d4 + 3] = v.w;
    }
    __syncthreads();
    // Phase B: transpose out of smem, coalesced [d][hw] stores
    float* outz = out + (size_t)b * Dd * HWp + hw0;
    #pragma unroll 8
    for (int it = 0; it < 128; it++) {
        int e = tid + it * 256;                // 32768 elements
        int d = e >> 7;
        int p = e & 127;
        outz[(size_t)d * HWp + p] = g_s[p * GS + d];  // banks (p+d)%32: conflict-free
    }
}

extern "C" void kernel_launch(void* const* d_in, const int* in_sizes, int n_in,
                              void* d_out, int out_size)
{
    const float* z   = (const float*)d_in[0];   // [8,256,64,64]
    const float* pw  = (const float*)d_in[1];   // [1024,256]
    const float* pb  = (const float*)d_in[2];   // [1024]
    const float* emb = (const float*)d_in[3];   // [1024,256]
    float* out = (float*)d_out;

    cudaFuncSetAttribute(aq_kernel, cudaFuncAttributeMaxDynamicSharedMemorySize, SMEM_BYTES);
    aq_kernel<<<PIX / TP, 256, SMEM_BYTES>>>(z, pw, pb, emb, out);
}